// round 16
// baseline (speedup 1.0000x reference)
#include <cuda_runtime.h>
#include <cuda_fp16.h>
#include <math.h>

#define N_NODES 50000
#define N_EDGES 800000
#define DIM 64
#define NGRAPH 512
#define GDIM 128
#define NBLK 196          // ceil(50000/256)

// d = a*b + d  on packed f32x2 (FFMA2)
#define FFMA2(ACC, A, B) \
    asm("fma.rn.f32x2 %0, %1, %2, %0;" : "+l"(ACC) : "l"(A), "l"(B))

// ---------------- scratch (static device arrays; no cudaMalloc) -------------
__device__ float  g_h[2][N_NODES * DIM];     // ping-pong node features
__device__ float  g_q[N_NODES * DIM];
// kv fp16, head-chunked: per node 16 uint4: chunk c (=ch/8, 0..7) has
// k(8 halves) at uint4 idx node*16+c*2, v(8 halves) at node*16+c*2+1
__device__ uint4  g_kv4[N_NODES * 16];
__device__ int    g_deg[N_NODES];
__device__ int    g_rowptr[N_NODES + 1];
__device__ int    g_cursor[N_NODES];
__device__ int2   g_edge[N_EDGES];           // (src, bitcast(edge_attr)) sorted by dst
__device__ int    g_bsum[NBLK];
__device__ int    g_boff[NBLK];
__device__ float  g_gsum[NGRAPH * DIM];
__device__ int    g_gcnt[NGRAPH];

// ---------------- CSR build -------------------------------------------------
__global__ void k_zero() {
    int i = blockIdx.x * blockDim.x + threadIdx.x;
    if (i < N_NODES) g_deg[i] = 0;
    if (i < NGRAPH * DIM) g_gsum[i] = 0.f;
    if (i < NGRAPH) g_gcnt[i] = 0;
}

__global__ void k_count(const int* __restrict__ edst, const int* __restrict__ batch) {
    int i = blockIdx.x * blockDim.x + threadIdx.x;
    if (i < N_EDGES) atomicAdd(&g_deg[edst[i]], 1);
    if (i < N_NODES) atomicAdd(&g_gcnt[batch[i]], 1);
}

__global__ __launch_bounds__(256) void k_scan1() {
    __shared__ int wsum[8];
    int b = blockIdx.x, t = threadIdx.x;
    int idx = b * 256 + t;
    int v = (idx < N_NODES) ? g_deg[idx] : 0;
    int lane = t & 31, w = t >> 5;
    int s = v;
#pragma unroll
    for (int o = 1; o < 32; o <<= 1) {
        int n = __shfl_up_sync(0xffffffffu, s, o);
        if (lane >= o) s += n;
    }
    if (lane == 31) wsum[w] = s;
    __syncthreads();
    if (w == 0) {
        int ws = (lane < 8) ? wsum[lane] : 0;
#pragma unroll
        for (int o = 1; o < 8; o <<= 1) {
            int n = __shfl_up_sync(0xffffffffu, ws, o);
            if (lane >= o) ws += n;
        }
        if (lane < 8) wsum[lane] = ws;
    }
    __syncthreads();
    int incl = s + (w ? wsum[w - 1] : 0);
    if (idx < N_NODES) g_rowptr[idx] = incl - v;
    if (t == 255) g_bsum[b] = incl;
}

__global__ __launch_bounds__(256) void k_scan2() {
    __shared__ int wsum[8];
    int t = threadIdx.x;
    int v = (t < NBLK) ? g_bsum[t] : 0;
    int lane = t & 31, w = t >> 5;
    int s = v;
#pragma unroll
    for (int o = 1; o < 32; o <<= 1) {
        int n = __shfl_up_sync(0xffffffffu, s, o);
        if (lane >= o) s += n;
    }
    if (lane == 31) wsum[w] = s;
    __syncthreads();
    if (w == 0) {
        int ws = (lane < 8) ? wsum[lane] : 0;
#pragma unroll
        for (int o = 1; o < 8; o <<= 1) {
            int n = __shfl_up_sync(0xffffffffu, ws, o);
            if (lane >= o) ws += n;
        }
        if (lane < 8) wsum[lane] = ws;
    }
    __syncthreads();
    int incl = s + (w ? wsum[w - 1] : 0);
    if (t < NBLK) g_boff[t] = incl - v;
    if (t == NBLK - 1) g_rowptr[N_NODES] = incl;
}

__global__ __launch_bounds__(256) void k_scan3() {
    int idx = blockIdx.x * 256 + threadIdx.x;
    if (idx < N_NODES) {
        int r = g_rowptr[idx] + g_boff[blockIdx.x];
        g_rowptr[idx] = r;
        g_cursor[idx] = r;
    }
}

__global__ void k_fill(const int* __restrict__ esrc, const int* __restrict__ edst,
                       const float* __restrict__ ea) {
    int i = blockIdx.x * blockDim.x + threadIdx.x;
    if (i < N_EDGES) {
        int p = atomicAdd(&g_cursor[edst[i]], 1);
        g_edge[p] = make_int2(esrc[i], __float_as_int(ea[i]));
    }
}

// ---------------- fused QKV+skip GEMM, FFMA2, 4 rows/warp -------------------
__global__ __launch_bounds__(256)
void k_gemm(const float* __restrict__ hin_ext, int inbuf, int outbuf,
            const float* __restrict__ Wq, const float* __restrict__ Wk,
            const float* __restrict__ Wv, const float* __restrict__ Wsk,
            const float* __restrict__ bq, const float* __restrict__ bk,
            const float* __restrict__ bv, const float* __restrict__ bsk) {
    extern __shared__ float smem[];
    float* Wsm = smem;              // 64*256
    float* bsm = smem + 64 * 256;   // 256
    int tid = threadIdx.x;
    for (int idx = tid; idx < 4096; idx += 256) {
        int kk = idx >> 6, j = idx & 63;
        Wsm[kk * 256 + j]       = Wq[idx];
        Wsm[kk * 256 + 64 + j]  = Wk[idx];
        Wsm[kk * 256 + 128 + j] = Wv[idx];
        Wsm[kk * 256 + 192 + j] = Wsk[idx];
    }
    if (tid < 64) {
        bsm[tid]       = bq[tid];
        bsm[64 + tid]  = bk[tid];
        bsm[128 + tid] = bv[tid];
        bsm[192 + tid] = bsk[tid];
    }
    __syncthreads();

    const float* hin = hin_ext ? hin_ext : (const float*)g_h[inbuf];
    float* hout = g_h[outbuf];

    int warp = tid >> 5, lane = tid & 31;
    int rbase = blockIdx.x * 32 + warp * 4;
    if (rbase >= N_NODES) return;

    float x0[4], x1[4];
#pragma unroll
    for (int r = 0; r < 4; r++) {
        int row = min(rbase + r, N_NODES - 1);
        x0[r] = hin[row * 64 + lane];
        x1[r] = hin[row * 64 + 32 + lane];
    }

    int jb = lane * 8;
    unsigned long long acc[4][4];
    {
        const ulonglong2* b2 = (const ulonglong2*)&bsm[jb];
        ulonglong2 ba = b2[0], bb = b2[1];
#pragma unroll
        for (int r = 0; r < 4; r++) {
            acc[r][0] = ba.x; acc[r][1] = ba.y;
            acc[r][2] = bb.x; acc[r][3] = bb.y;
        }
    }

#pragma unroll
    for (int kk = 0; kk < 32; kk++) {
        const ulonglong2* w2 = (const ulonglong2*)&Wsm[kk * 256 + jb];
        ulonglong2 wa = w2[0], wb = w2[1];
#pragma unroll
        for (int r = 0; r < 4; r++) {
            float xk = __shfl_sync(0xffffffffu, x0[r], kk);
            unsigned long long xx;
            asm("mov.b64 %0, {%1, %1};" : "=l"(xx) : "r"(__float_as_uint(xk)));
            FFMA2(acc[r][0], xx, wa.x);
            FFMA2(acc[r][1], xx, wa.y);
            FFMA2(acc[r][2], xx, wb.x);
            FFMA2(acc[r][3], xx, wb.y);
        }
    }
#pragma unroll
    for (int kk = 0; kk < 32; kk++) {
        const ulonglong2* w2 = (const ulonglong2*)&Wsm[(kk + 32) * 256 + jb];
        ulonglong2 wa = w2[0], wb = w2[1];
#pragma unroll
        for (int r = 0; r < 4; r++) {
            float xk = __shfl_sync(0xffffffffu, x1[r], kk);
            unsigned long long xx;
            asm("mov.b64 %0, {%1, %1};" : "=l"(xx) : "r"(__float_as_uint(xk)));
            FFMA2(acc[r][0], xx, wa.x);
            FFMA2(acc[r][1], xx, wa.y);
            FFMA2(acc[r][2], xx, wb.x);
            FFMA2(acc[r][3], xx, wb.y);
        }
    }

    int m = jb >> 6, c = jb & 63;
#pragma unroll
    for (int r = 0; r < 4; r++) {
        int row = rbase + r;
        if (row >= N_NODES) break;
        float2 p0 = *(float2*)&acc[r][0];
        float2 p1 = *(float2*)&acc[r][1];
        float2 p2 = *(float2*)&acc[r][2];
        float2 p3 = *(float2*)&acc[r][3];
        if (m == 0) {
            *(float4*)&g_q[row * 64 + c]     = make_float4(p0.x, p0.y, p1.x, p1.y);
            *(float4*)&g_q[row * 64 + c + 4] = make_float4(p2.x, p2.y, p3.x, p3.y);
        } else if (m == 3) {
            *(float4*)&hout[row * 64 + c]     = make_float4(p0.x, p0.y, p1.x, p1.y);
            *(float4*)&hout[row * 64 + c + 4] = make_float4(p2.x, p2.y, p3.x, p3.y);
        } else {
            // head-chunked fp16 kv: lane's 8 channels = exactly one chunk
            __half2 h0 = __float22half2_rn(p0);
            __half2 h1 = __float22half2_rn(p1);
            __half2 h2 = __float22half2_rn(p2);
            __half2 h3 = __float22half2_rn(p3);
            uint4 pk;
            pk.x = *(unsigned*)&h0; pk.y = *(unsigned*)&h1;
            pk.z = *(unsigned*)&h2; pk.w = *(unsigned*)&h3;
            g_kv4[row * 16 + ((c >> 3) << 1) + ((m == 2) ? 1 : 0)] = pk;
        }
    }
}

// ---------------- per-node attention v3: lane = (slot, chunk) ----------------
// warp per node; lane = slot*8 + chunk; chunk owns 8 channels (half a head);
// 4 edges per warp-step (one per slot), 1 shfl per edge-pair for the dot.
__device__ __forceinline__ void h8f(uint4 u, float* f) {
    float2 a = __half22float2(*(const __half2*)&u.x);
    float2 b = __half22float2(*(const __half2*)&u.y);
    float2 c = __half22float2(*(const __half2*)&u.z);
    float2 d = __half22float2(*(const __half2*)&u.w);
    f[0] = a.x; f[1] = a.y; f[2] = b.x; f[3] = b.y;
    f[4] = c.x; f[5] = c.y; f[6] = d.x; f[7] = d.y;
}

__global__ __launch_bounds__(256)
void k_attn(const float* __restrict__ Wel, const int* __restrict__ batch,
            int iobuf, float* __restrict__ out_nodes, int mode) {
    int node = (blockIdx.x * 256 + threadIdx.x) >> 5;
    int lane = threadIdx.x & 31;
    if (node >= N_NODES) return;
    int slot = lane >> 3;      // which edge of the 4 in flight
    int chunk = lane & 7;      // channels [chunk*8, chunk*8+8); head = chunk>>1

    float q[8], we[8];
    {
        const float4* qp = (const float4*)&g_q[node * 64 + chunk * 8];
        float4 qa = qp[0], qb = qp[1];
        q[0] = qa.x * 0.25f; q[1] = qa.y * 0.25f; q[2] = qa.z * 0.25f; q[3] = qa.w * 0.25f;
        q[4] = qb.x * 0.25f; q[5] = qb.y * 0.25f; q[6] = qb.z * 0.25f; q[7] = qb.w * 0.25f;
        const float4* wp = (const float4*)&Wel[chunk * 8];
        float4 wa = wp[0], wb = wp[1];
        we[0] = wa.x; we[1] = wa.y; we[2] = wa.z; we[3] = wa.w;
        we[4] = wb.x; we[5] = wb.y; we[6] = wb.z; we[7] = wb.w;
    }
    float qw2 = 0.f;
#pragma unroll
    for (int j = 0; j < 8; j++) qw2 = fmaf(q[j], we[j], qw2);  // lane partial of (q.we)/4

    int beg = g_rowptr[node], end = g_rowptr[node + 1];

    float d = 0.f, t = 0.f;
    float acc[8];
#pragma unroll
    for (int j = 0; j < 8; j++) acc[j] = 0.f;

    for (int base = beg; base < end; base += 8) {
        int i0 = base + slot, i1 = base + 4 + slot;
        bool act0 = i0 < end, act1 = i1 < end;
        int2 E0 = g_edge[act0 ? i0 : beg];
        int2 E1 = g_edge[act1 ? i1 : beg];
        int b0 = E0.x * 16 + chunk * 2, b1 = E1.x * 16 + chunk * 2;
        uint4 ku0 = g_kv4[b0], vu0 = g_kv4[b0 + 1];
        uint4 ku1 = g_kv4[b1], vu1 = g_kv4[b1 + 1];
        float av0 = __int_as_float(E0.y), av1 = __int_as_float(E1.y);

        float kf0[8], kf1[8];
        h8f(ku0, kf0); h8f(ku1, kf1);
        float p0 = av0 * qw2, p1 = av1 * qw2;
#pragma unroll
        for (int j = 0; j < 8; j++) {
            p0 = fmaf(q[j], kf0[j], p0);
            p1 = fmaf(q[j], kf1[j], p1);
        }
        p0 += __shfl_xor_sync(0xffffffffu, p0, 1);
        p1 += __shfl_xor_sync(0xffffffffu, p1, 1);
        float w0 = act0 ? __expf(p0) : 0.f;
        float w1 = act1 ? __expf(p1) : 0.f;
        d += w0 + w1;
        t = fmaf(w0, av0, t);
        t = fmaf(w1, av1, t);
        float vf0[8], vf1[8];
        h8f(vu0, vf0); h8f(vu1, vf1);
#pragma unroll
        for (int j = 0; j < 8; j++) {
            acc[j] = fmaf(w0, vf0[j], acc[j]);
            acc[j] = fmaf(w1, vf1[j], acc[j]);
        }
    }

    // reduce across the 4 slots (lane bits 3,4)
#pragma unroll
    for (int off = 8; off < 32; off <<= 1) {
        d += __shfl_xor_sync(0xffffffffu, d, off);
        t += __shfl_xor_sync(0xffffffffu, t, off);
#pragma unroll
        for (int j = 0; j < 8; j++)
            acc[j] += __shfl_xor_sync(0xffffffffu, acc[j], off);
    }

    if (slot == 0) {
        float inv = 1.f / (d + 1e-16f);
        float* hio = g_h[iobuf];
        int gi = node * 64 + chunk * 8;
        float4 ha = *(const float4*)&hio[gi];
        float4 hb = *(const float4*)&hio[gi + 4];
        float o[8];
        o[0] = ha.x; o[1] = ha.y; o[2] = ha.z; o[3] = ha.w;
        o[4] = hb.x; o[5] = hb.y; o[6] = hb.z; o[7] = hb.w;
#pragma unroll
        for (int j = 0; j < 8; j++) {
            o[j] += (acc[j] + we[j] * t) * inv;
            if (mode == 0) o[j] = fmaxf(o[j], 0.f);
        }
        *(float4*)&hio[gi]     = make_float4(o[0], o[1], o[2], o[3]);
        *(float4*)&hio[gi + 4] = make_float4(o[4], o[5], o[6], o[7]);
        if (mode == 1) {
            *(float4*)&out_nodes[gi]     = make_float4(o[0], o[1], o[2], o[3]);
            *(float4*)&out_nodes[gi + 4] = make_float4(o[4], o[5], o[6], o[7]);
            int g = batch[node];
#pragma unroll
            for (int j = 0; j < 8; j++)
                atomicAdd(&g_gsum[g * 64 + chunk * 8 + j], o[j]);
        }
    }
}

// ---------------- mean pool + graph MLP -------------------------------------
__global__ __launch_bounds__(128)
void k_mlp(const float* __restrict__ W1, const float* __restrict__ b1,
           const float* __restrict__ W2, const float* __restrict__ b2,
           const float* __restrict__ W3, const float* __restrict__ b3,
           float* __restrict__ out_g) {
    __shared__ float gm[64], h1[64], h2[16];
    int g = blockIdx.x, t = threadIdx.x;
    if (t < 64) {
        float cnt = fmaxf((float)g_gcnt[g], 1.f);
        gm[t] = g_gsum[g * 64 + t] / cnt;
    }
    __syncthreads();
    if (t < 64) {
        float acc = b1[t];
#pragma unroll 8
        for (int k = 0; k < 64; k++) acc += gm[k] * W1[k * 64 + t];
        h1[t] = fmaxf(acc, 0.f);
    }
    __syncthreads();
    if (t < 16) {
        float acc = b2[t];
#pragma unroll 8
        for (int k = 0; k < 64; k++) acc += h1[k] * W2[k * 16 + t];
        h2[t] = fmaxf(acc, 0.f);
    }
    __syncthreads();
    {
        float acc = b3[t];
#pragma unroll
        for (int k = 0; k < 16; k++) acc += h2[k] * W3[k * 128 + t];
        out_g[g * 128 + t] = acc;
    }
}

// ---------------- host ------------------------------------------------------
extern "C" void kernel_launch(void* const* d_in, const int* in_sizes, int n_in,
                              void* d_out, int out_size) {
    const float *x = 0, *ea = 0;
    const int *eidx = 0, *batch = 0;
    const float *Wq = 0, *bq = 0, *Wk = 0, *bk = 0, *Wv = 0, *bv = 0;
    const float *We = 0, *Wsk = 0, *bsk = 0;
    const float *W1 = 0, *b1 = 0, *W2 = 0, *b2 = 0, *W3 = 0, *b3 = 0;
    int n12288 = 0, n192 = 0;
    for (int i = 0; i < n_in; i++) {
        int sz = in_sizes[i];
        const void* p = d_in[i];
        switch (sz) {
            case 3200000: x = (const float*)p; break;
            case 800000:  ea = (const float*)p; break;
            case 1600000: eidx = (const int*)p; break;
            case 50000:   batch = (const int*)p; break;
            case 12288: {
                const float* f = (const float*)p;
                if (n12288 == 0) Wq = f; else if (n12288 == 1) Wk = f;
                else if (n12288 == 2) Wv = f; else Wsk = f;
                n12288++;
            } break;
            case 192: {
                const float* f = (const float*)p;
                if (n192 == 0) bq = f; else if (n192 == 1) bk = f;
                else if (n192 == 2) bv = f; else if (n192 == 3) We = f;
                else bsk = f;
                n192++;
            } break;
            case 4096: W1 = (const float*)p; break;
            case 64:   b1 = (const float*)p; break;
            case 1024: W2 = (const float*)p; break;
            case 16:   b2 = (const float*)p; break;
            case 2048: W3 = (const float*)p; break;
            case 128:  b3 = (const float*)p; break;
        }
    }
    const int* esrc = eidx;
    const int* edst = eidx + N_EDGES;
    float* out_nodes = (float*)d_out;
    float* out_graph = out_nodes + (size_t)N_NODES * DIM;

    const int smem_gemm = (64 * 256 + 256) * sizeof(float);  // 66560 B
    cudaFuncSetAttribute(k_gemm, cudaFuncAttributeMaxDynamicSharedMemorySize, smem_gemm);

    // CSR by destination + graph counts
    k_zero<<<(N_NODES + 255) / 256, 256>>>();
    k_count<<<(N_EDGES + 255) / 256, 256>>>(edst, batch);
    k_scan1<<<NBLK, 256>>>();
    k_scan2<<<1, 256>>>();
    k_scan3<<<NBLK, 256>>>();
    k_fill<<<(N_EDGES + 255) / 256, 256>>>(esrc, edst, ea);

    const int gemm_grid = (N_NODES + 31) / 32;
    const int attn_grid = (N_NODES * 32 + 255) / 256;

    // layer 0: input = x -> skip in g_h[0]
    k_gemm<<<gemm_grid, 256, smem_gemm>>>(x, 0, 0,
        Wq + 0 * 4096, Wk + 0 * 4096, Wv + 0 * 4096, Wsk + 0 * 4096,
        bq + 0 * 64, bk + 0 * 64, bv + 0 * 64, bsk + 0 * 64);
    k_attn<<<attn_grid, 256>>>(We + 0 * 64, batch, 0, out_nodes, 0);

    // layer 1: g_h[0] -> g_h[1]
    k_gemm<<<gemm_grid, 256, smem_gemm>>>(nullptr, 0, 1,
        Wq + 1 * 4096, Wk + 1 * 4096, Wv + 1 * 4096, Wsk + 1 * 4096,
        bq + 1 * 64, bk + 1 * 64, bv + 1 * 64, bsk + 1 * 64);
    k_attn<<<attn_grid, 256>>>(We + 1 * 64, batch, 1, out_nodes, 0);

    // layer 2 (last): g_h[1] -> g_h[0]; writes node embeddings + pooling sums
    k_gemm<<<gemm_grid, 256, smem_gemm>>>(nullptr, 1, 0,
        Wq + 2 * 4096, Wk + 2 * 4096, Wv + 2 * 4096, Wsk + 2 * 4096,
        bq + 2 * 64, bk + 2 * 64, bv + 2 * 64, bsk + 2 * 64);
    k_attn<<<attn_grid, 256>>>(We + 2 * 64, batch, 0, out_nodes, 1);

    // mean pool + MLP head
    k_mlp<<<NGRAPH, 128>>>(W1, b1, W2, b2, W3, b3, out_graph);
}